// round 6
// baseline (speedup 1.0000x reference)
#include <cuda_runtime.h>
#include <cstdint>

#define N_ANCH 102000
#define ROWLEN 85
#define CONF 0.25f
#define IOUT 0.45f
#define TOPK 8192
#define KW 128            // 8192/64 words per mask row
#define MAXDET 300
#define CAP 16384
#define NBIN 65536

typedef unsigned long long u64;
typedef unsigned int u32;

// ---------------- static device scratch ----------------
__device__ u64 g_keys[N_ANCH];
__device__ u32 g_cls[N_ANCH];
__device__ u32 g_hist[NBIN];
__device__ u32 g_binoff[NBIN];
__device__ u32 g_bincnt[NBIN];
__device__ int g_thrbin;
__device__ u64 g_slot[CAP];
__device__ float4 g_boxes[TOPK];
__device__ float g_scores[TOPK];
__device__ float g_classes[TOPK];
__device__ u64 g_validm[KW];
__device__ u64 g_mask[(size_t)TOPK * KW];   // 8 MB (L2-resident)

// ---------------- K0: zero per-call state ----------------
__global__ void k_init() {
    int t = blockIdx.x * blockDim.x + threadIdx.x;   // 65536 threads
    g_hist[t] = 0u;
    g_bincnt[t] = 0u;
    if (t < CAP) g_slot[t] = 0ULL;
    if (t < KW) g_validm[t] = 0ULL;
    if (t == 0) g_thrbin = 0;
}

// ---------------- K1: score/class + key + 16-bit histogram ----------------
__global__ void k_score(const float* __restrict__ preds) {
    int warp = (blockIdx.x * blockDim.x + threadIdx.x) >> 5;
    int lane = threadIdx.x & 31;
    if (warp >= N_ANCH) return;
    const float* p = preds + (size_t)warp * ROWLEN;
    float e0 = p[lane];
    float obj = __shfl_sync(0xffffffffu, e0, 4);
    u32 sb = 0; int bc = 0;
    if (obj > CONF) {
        float e1 = p[lane + 32];
        float e2 = (lane < 21) ? p[lane + 64] : 0.0f;
        float bv = -1.0f;
        if (lane >= 5) { bv = e0 * obj; bc = lane - 5; }
        float v1 = e1 * obj;
        if (v1 > bv) { bv = v1; bc = lane + 27; }
        if (lane < 21) { float v2 = e2 * obj; if (v2 > bv) { bv = v2; bc = lane + 59; } }
        u32 vb = __float_as_uint(bv);
        u32 m = __reduce_max_sync(0xffffffffu, vb);
        u32 cm = __reduce_min_sync(0xffffffffu, (vb == m) ? (u32)bc : 0xFFFFu);
        sb = m; bc = (int)cm;
    }
    if (lane == 0) {
        g_keys[warp] = ((u64)sb << 32) | (u64)(0xFFFFFFFFu - (u32)warp);
        g_cls[warp] = (u32)bc;
        if (sb) atomicAdd(&g_hist[sb >> 16], 1u);
    }
}

// ---------------- K2: threshold bin + per-bin descending exclusive offsets ----------------
__global__ void k_thresh() {
    __shared__ u32 part[1024];
    int t = threadIdx.x;
    u32 s = 0;
    #pragma unroll
    for (int b = 0; b < 64; b++) s += g_hist[t * 64 + b];
    part[t] = s;
    __syncthreads();
    for (int off = 1; off < 1024; off <<= 1) {   // inclusive suffix sum of chunks
        u32 v = part[t] + ((t + off < 1024) ? part[t + off] : 0u);
        __syncthreads();
        part[t] = v;
        __syncthreads();
    }
    u32 sufNext = (t < 1023) ? part[t + 1] : 0u;
    if (part[t] >= TOPK && sufNext < TOPK) {
        u32 acc = sufNext;
        for (int b = 63; b >= 0; b--) {
            acc += g_hist[t * 64 + b];
            if (acc >= TOPK) { g_thrbin = t * 64 + b; break; }
        }
    }
    if (t == 0 && part[0] < TOPK) g_thrbin = 0;
    u32 acc = sufNext;
    for (int b = 63; b >= 0; b--) {
        g_binoff[t * 64 + b] = acc;
        acc += g_hist[t * 64 + b];
    }
}

// ---------------- K3: place candidates into bin regions ----------------
__global__ void k_place() {
    int i = blockIdx.x * blockDim.x + threadIdx.x;
    if (i >= N_ANCH) return;
    u64 k = g_keys[i];
    u32 sb = (u32)(k >> 32);
    if (!sb) return;
    int bin = (int)(sb >> 16);
    if (bin < g_thrbin) return;
    u32 p = g_binoff[bin] + atomicAdd(&g_bincnt[bin], 1u);
    if (p < CAP) g_slot[p] = k;
}

// ---------------- K4: within-bin rank + direct gather/write ----------------
__global__ void k_sortbins(const float* __restrict__ preds) {
    int p = blockIdx.x * blockDim.x + threadIdx.x;
    if (p >= CAP) return;
    u64 k = g_slot[p];
    if (!k) return;
    int bin = (int)(k >> 48);
    u32 off = g_binoff[bin];
    u32 cnt = g_bincnt[bin];
    u32 end = off + cnt; if (end > CAP) end = CAP;
    u32 r = off;
    for (u32 q = off; q < end; q++) r += (g_slot[q] > k) ? 1u : 0u;
    if (r >= TOPK) return;
    u32 idx = 0xFFFFFFFFu - (u32)k;
    float s = __uint_as_float((u32)(k >> 32));
    const float* pr = preds + (size_t)idx * ROWLEN;
    float x = pr[0], y = pr[1], w = pr[2], h = pr[3];
    float4 b;
    b.x = y - h * 0.5f;
    b.y = x - w * 0.5f;
    b.z = y + h * 0.5f;
    b.w = x + w * 0.5f;
    g_boxes[r] = b;
    g_scores[r] = s;
    g_classes[r] = (float)g_cls[idx];
    atomicOr(&g_validm[r >> 6], 1ULL << (r & 63));
}

// ---------------- K5: full IoU bitmask (upper-triangular 64x64 tiles) ----------------
__global__ void k_mask() {
    int cy = blockIdx.y, cx = blockIdx.x;
    if (cx < cy) return;
    int t = threadIdx.x;  // 64
    __shared__ float4 sb4[64];
    __shared__ float sa[64];
    float4 jb = g_boxes[cx * 64 + t];
    sb4[t] = jb;
    sa[t] = (jb.z - jb.x) * (jb.w - jb.y);
    float4 ib = g_boxes[cy * 64 + t];
    float ai = (ib.z - ib.x) * (ib.w - ib.y);
    __syncthreads();
    u64 bits = 0;
    int jstart = (cx == cy) ? t + 1 : 0;
    for (int j = jstart; j < 64; j++) {
        float4 b2 = sb4[j];
        float ty = fmaxf(ib.x, b2.x);
        float tx = fmaxf(ib.y, b2.y);
        float by = fminf(ib.z, b2.z);
        float bx = fminf(ib.w, b2.w);
        float inter = fmaxf(by - ty, 0.0f) * fmaxf(bx - tx, 0.0f);
        float uni = ai + sa[j] - inter;
        float iou = inter / (uni + 1e-9f);
        if (iou > IOUT) bits |= (1ULL << j);
    }
    g_mask[(size_t)(cy * 64 + t) * KW + cx] = bits;
}

// ---------------- K6: serial greedy scan (verified R2 structure) + fused output ----------------
__global__ void k_scan(float* __restrict__ out) {
    __shared__ u64 sAlive;
    __shared__ int sKept[MAXDET];
    __shared__ int sNk;
    int t = threadIdx.x;  // 128 threads, thread w owns remv word w
    u64 remv = 0;
    int nk = 0;
    bool done = false;
    for (int c = 0; c < KW && !done; c++) {
        if (t == c) sAlive = (~remv) & g_validm[c];
        __syncthreads();
        while (true) {
            u64 a = sAlive;
            if (a == 0ULL) break;
            int bit = __ffsll((long long)a) - 1;
            int i = (c << 6) + bit;
            u64 row = (t >= c) ? g_mask[(size_t)i * KW + t] : 0ULL;
            remv |= row;
            if (t == 0) sKept[nk] = i;
            nk++;
            if (t == c) sAlive = a & ~(1ULL << bit) & ~row;
            __syncthreads();
            if (nk >= MAXDET) { done = true; break; }
        }
        __syncthreads();
    }
    if (t == 0) sNk = nk < MAXDET ? nk : MAXDET;
    __syncthreads();
    int n = sNk;
    for (int s = t; s < MAXDET; s += 128) {
        float4 b = make_float4(0.f, 0.f, 0.f, 0.f);
        float cls = 0.f, sc = 0.f;
        if (s < n) {
            int i = sKept[s];
            b = g_boxes[i]; cls = g_classes[i]; sc = g_scores[i];
        }
        out[s * 4 + 0] = b.x; out[s * 4 + 1] = b.y;
        out[s * 4 + 2] = b.z; out[s * 4 + 3] = b.w;
        out[MAXDET * 4 + s] = cls;
        out[MAXDET * 5 + s] = sc;
    }
}

extern "C" void kernel_launch(void* const* d_in, const int* in_sizes, int n_in,
                              void* d_out, int out_size) {
    const float* preds = (const float*)d_in[0];
    float* out = (float*)d_out;

    k_init<<<256, 256>>>();
    k_score<<<(N_ANCH + 7) / 8, 256>>>(preds);
    k_thresh<<<1, 1024>>>();
    k_place<<<(N_ANCH + 255) / 256, 256>>>();
    k_sortbins<<<CAP / 256, 256>>>(preds);
    k_mask<<<dim3(128, 128), 64>>>();
    k_scan<<<1, 128>>>(out);
}

// round 7
// speedup vs baseline: 2.5813x; 2.5813x over previous
#include <cuda_runtime.h>
#include <cstdint>

#define N_ANCH 102000
#define ROWLEN 85
#define CONF 0.25f
#define IOUT 0.45f
#define TOPK 8192
#define KW 128            // 8192/64 mask words per row (full fallback)
#define KWS 16            // 1024/64 words, small fast-path mask
#define NSMALL 1024
#define MAXDET 300
#define CAP 9216          // candidate cap after 16-bit histogram select
#define NBIN 65536

typedef unsigned long long u64;
typedef unsigned int u32;

// ---------------- static device scratch ----------------
__device__ u64 g_keys[N_ANCH];
__device__ u32 g_cls[N_ANCH];
__device__ u32 g_hist[NBIN];
__device__ int g_thrbin;
__device__ int g_cnt;
__device__ u64 g_ckeys[CAP];
__device__ u32 g_rank[CAP];
__device__ u64 g_topkeys[TOPK];
__device__ float4 g_boxes[TOPK];
__device__ float g_scores[TOPK];
__device__ float g_classes[TOPK];
__device__ u64 g_validm[KW];
__device__ u64 g_maskS[(size_t)NSMALL * KWS];   // 128 KB fast path
__device__ u64 g_mask[(size_t)TOPK * KW];       // 8 MB fallback
__device__ int g_kept[MAXDET];
__device__ int g_nkept;
__device__ int g_done;

// ---------------- K0: zero per-call state ----------------
__global__ void k_init() {
    int t = blockIdx.x * blockDim.x + threadIdx.x;   // 65536 threads
    g_hist[t] = 0u;
    if (t < CAP) { g_ckeys[t] = 0ULL; g_rank[t] = 0u; }
    if (t < TOPK) g_topkeys[t] = 0ULL;
    if (t < KW) g_validm[t] = 0ULL;
    if (t == 0) { g_cnt = 0; g_nkept = 0; g_thrbin = 0; g_done = 0; }
}

// ---------------- K1: score/class + key + 16-bit histogram ----------------
__global__ void k_score(const float* __restrict__ preds) {
    int warp = (blockIdx.x * blockDim.x + threadIdx.x) >> 5;
    int lane = threadIdx.x & 31;
    if (warp >= N_ANCH) return;
    const float* p = preds + (size_t)warp * ROWLEN;
    float e0 = p[lane];
    float obj = __shfl_sync(0xffffffffu, e0, 4);
    u32 sb = 0; int bc = 0;
    if (obj > CONF) {
        float e1 = p[lane + 32];
        float e2 = (lane < 21) ? p[lane + 64] : 0.0f;
        float bv = -1.0f;
        if (lane >= 5) { bv = e0 * obj; bc = lane - 5; }
        float v1 = e1 * obj;
        if (v1 > bv) { bv = v1; bc = lane + 27; }
        if (lane < 21) { float v2 = e2 * obj; if (v2 > bv) { bv = v2; bc = lane + 59; } }
        u32 vb = __float_as_uint(bv);
        u32 m = __reduce_max_sync(0xffffffffu, vb);
        u32 cm = __reduce_min_sync(0xffffffffu, (vb == m) ? (u32)bc : 0xFFFFu);
        sb = m; bc = (int)cm;
    }
    if (lane == 0) {
        g_keys[warp] = ((u64)sb << 32) | (u64)(0xFFFFFFFFu - (u32)warp);
        g_cls[warp] = (u32)bc;
        if (sb) atomicAdd(&g_hist[sb >> 16], 1u);
    }
}

// ---------------- K2: threshold bin over 65536 bins ----------------
__global__ void k_thresh() {
    __shared__ u32 part[1024];
    int t = threadIdx.x;
    u32 s = 0;
    #pragma unroll
    for (int b = 0; b < 64; b++) s += g_hist[t * 64 + b];
    part[t] = s;
    __syncthreads();
    for (int off = 1; off < 1024; off <<= 1) {   // suffix sum
        u32 v = part[t] + ((t + off < 1024) ? part[t + off] : 0u);
        __syncthreads();
        part[t] = v;
        __syncthreads();
    }
    u32 suf = part[t];
    u32 sufNext = (t < 1023) ? part[t + 1] : 0u;
    if (suf >= TOPK && sufNext < TOPK) {
        u32 acc = sufNext;
        for (int b = 63; b >= 0; b--) {
            acc += g_hist[t * 64 + b];
            if (acc >= TOPK) { g_thrbin = t * 64 + b; break; }
        }
    }
    if (t == 0 && part[0] < TOPK) g_thrbin = 0;
}

// ---------------- K3: compact (warp-aggregated atomic) ----------------
__global__ void k_compact() {
    int i = blockIdx.x * blockDim.x + threadIdx.x;
    bool take = false; u64 k = 0;
    if (i < N_ANCH) {
        k = g_keys[i];
        take = ((int)(k >> 48) >= g_thrbin) && ((u32)(k >> 32) != 0u);
    }
    u32 bal = __ballot_sync(0xffffffffu, take);
    if (!bal) return;
    int lane = threadIdx.x & 31;
    int leader = __ffs(bal) - 1;
    int pos0 = 0;
    if (lane == leader) pos0 = atomicAdd(&g_cnt, __popc(bal));
    pos0 = __shfl_sync(0xffffffffu, pos0, leader);
    if (take) {
        int pos = pos0 + __popc(bal & ((1u << lane) - 1u));
        if (pos < CAP) g_ckeys[pos] = k;
    }
}

// ---------------- K4: all-pairs rank ----------------
#define RCHI 1024
#define RCHJ 768
__global__ void k_rank() {
    __shared__ u64 sj[RCHJ];
    int t = threadIdx.x;
    int ibase = blockIdx.x * RCHI;
    int jbase = blockIdx.y * RCHJ;
    for (int j = t; j < RCHJ; j += 256) sj[j] = g_ckeys[jbase + j];
    __syncthreads();
    u64 ki[4]; u32 r[4];
    #pragma unroll
    for (int q = 0; q < 4; q++) { ki[q] = g_ckeys[ibase + q * 256 + t]; r[q] = 0; }
    #pragma unroll 4
    for (int j = 0; j < RCHJ; j++) {
        u64 kj = sj[j];
        #pragma unroll
        for (int q = 0; q < 4; q++) r[q] += (kj > ki[q]) ? 1u : 0u;
    }
    #pragma unroll
    for (int q = 0; q < 4; q++) atomicAdd(&g_rank[ibase + q * 256 + t], r[q]);
}

__global__ void k_scatter() {
    int i = blockIdx.x * blockDim.x + threadIdx.x;
    if (i >= CAP) return;
    u32 r = g_rank[i];
    if (r < TOPK) g_topkeys[r] = g_ckeys[i];
}

// ---------------- K5: gather ----------------
__global__ void k_gather(const float* __restrict__ preds) {
    int r = blockIdx.x * blockDim.x + threadIdx.x;
    if (r >= TOPK) return;
    u64 key = g_topkeys[r];
    float s = __uint_as_float((u32)(key >> 32));
    u32 idx = 0xFFFFFFFFu - (u32)key;
    bool valid = (s > 0.0f) && (idx < N_ANCH);
    if (idx >= N_ANCH) idx = 0;
    const float* p = preds + (size_t)idx * ROWLEN;
    float x = p[0], y = p[1], w = p[2], h = p[3];
    float4 b;
    b.x = y - h * 0.5f;
    b.y = x - w * 0.5f;
    b.z = y + h * 0.5f;
    b.w = x + w * 0.5f;
    g_boxes[r] = b;
    g_scores[r] = s;
    g_classes[r] = (float)g_cls[idx];
    if (valid) atomicOr(&g_validm[r >> 6], 1ULL << (r & 63));
}

// ---------------- IoU helper (exact reference arithmetic) ----------------
__device__ __forceinline__ u64 iou_bits(float4 ib, float ai, const float4* sb4,
                                        const float* sa, int jstart) {
    u64 bits = 0;
    for (int j = jstart; j < 64; j++) {
        float4 b2 = sb4[j];
        float ty = fmaxf(ib.x, b2.x);
        float tx = fmaxf(ib.y, b2.y);
        float by = fminf(ib.z, b2.z);
        float bx = fminf(ib.w, b2.w);
        float inter = fmaxf(by - ty, 0.0f) * fmaxf(bx - tx, 0.0f);
        float uni = ai + sa[j] - inter;
        float iou = inter / (uni + 1e-9f);
        if (iou > IOUT) bits |= (1ULL << j);
    }
    return bits;
}

// ---------------- K6a: fast-path mask (top 1024 x 1024) ----------------
__global__ void k_maskS() {
    int cy = blockIdx.y, cx = blockIdx.x;
    if (cx < cy) return;
    int t = threadIdx.x;
    __shared__ float4 sb4[64];
    __shared__ float sa[64];
    float4 jb = g_boxes[cx * 64 + t];
    sb4[t] = jb;
    sa[t] = (jb.z - jb.x) * (jb.w - jb.y);
    float4 ib = g_boxes[cy * 64 + t];
    float ai = (ib.z - ib.x) * (ib.w - ib.y);
    __syncthreads();
    u64 bits = iou_bits(ib, ai, sb4, sa, (cx == cy) ? t + 1 : 0);
    g_maskS[(size_t)(cy * 64 + t) * KWS + cx] = bits;
}

// ---------------- K6b: fast-path scan (single warp, smem mask) + fused output ----------------
__global__ void k_scanS(float* __restrict__ out) {
    extern __shared__ u64 srow[];            // NSMALL*KWS u64 = 128 KB
    __shared__ u64 sVtail;
    __shared__ int sKept[MAXDET];
    __shared__ int sNk, sDone;
    int t = threadIdx.x;                     // 512 threads
    if (t == 0) sVtail = 0ULL;
    __syncthreads();
    for (int i = t; i < NSMALL * KWS; i += 512) srow[i] = g_maskS[i];
    u64 vt = 0;
    for (int w = KWS + t; w < KW; w += 512) vt |= g_validm[w];
    if (vt) atomicOr(&sVtail, vt);
    __syncthreads();
    if (t < 32) {
        int lane = t;
        u64 avail = (lane < KWS) ? g_validm[lane] : 0ULL;
        int nk = 0;
        bool exhausted = false;
        while (nk < MAXDET) {
            u32 bal = __ballot_sync(0xffffffffu, avail != 0ULL);
            if (!bal) { exhausted = true; break; }
            int c = __ffs(bal) - 1;
            u64 aw = __shfl_sync(0xffffffffu, avail, c);
            int b0 = __ffsll((long long)aw) - 1;  u64 aw1 = aw & (aw - 1);
            int b1 = __ffsll((long long)aw1) - 1; u64 aw2 = aw1 & (aw1 - 1);
            int b2 = __ffsll((long long)aw2) - 1; u64 aw3 = aw2 & (aw2 - 1);
            int b3 = __ffsll((long long)aw3) - 1;
            int m = 1 + (aw1 != 0ULL) + (aw2 != 0ULL) + (aw3 != 0ULL);
            int i0 = (c << 6) + b0, i1 = (c << 6) + b1;
            int i2 = (c << 6) + b2, i3 = (c << 6) + b3;
            bool rd = (lane >= c) && (lane < KWS);
            u64 r0 = rd ? srow[i0 * KWS + lane] : 0ULL;
            u64 r1 = (rd && m > 1) ? srow[i1 * KWS + lane] : 0ULL;
            u64 r2 = (rd && m > 2) ? srow[i2 * KWS + lane] : 0ULL;
            u64 r3 = (rd && m > 3) ? srow[i3 * KWS + lane] : 0ULL;
            u32 kmask = 0;
            if (lane == c) {
                u64 sup = r0;
                int k1 = (m > 1) && !((sup >> b1) & 1ULL); if (k1) sup |= r1;
                int k2 = (m > 2) && !((sup >> b2) & 1ULL); if (k2) sup |= r2;
                int k3 = (m > 3) && !((sup >> b3) & 1ULL);
                kmask = 1u | (u32)(k1 << 1) | (u32)(k2 << 2) | (u32)(k3 << 3);
            }
            kmask = __shfl_sync(0xffffffffu, kmask, c);
            int k1 = (kmask >> 1) & 1, k2 = (kmask >> 2) & 1, k3 = (kmask >> 3) & 1;
            u64 sup = r0 | (k1 ? r1 : 0ULL) | (k2 ? r2 : 0ULL) | (k3 ? r3 : 0ULL);
            if (lane == c) avail = aw3 & (aw3 - 1);
            avail &= ~sup;
            int allowed = MAXDET - nk;
            if (lane == 0) {
                int w = 0;
                if (w < allowed) { sKept[nk + w] = i0; w++; }
                if (k1 && w < allowed) { sKept[nk + w] = i1; w++; }
                if (k2 && w < allowed) { sKept[nk + w] = i2; w++; }
                if (k3 && w < allowed) { sKept[nk + w] = i3; w++; }
            }
            nk += 1 + k1 + k2 + k3;
        }
        if (lane == 0) {
            int n = nk < MAXDET ? nk : MAXDET;
            sNk = n;
            sDone = (nk >= MAXDET || (exhausted && sVtail == 0ULL)) ? 1 : 0;
            g_done = sDone;
            g_nkept = n;
        }
    }
    __syncthreads();
    if (!sDone) return;
    int nk = sNk;
    for (int s = t; s < MAXDET; s += 512) {
        float4 b = make_float4(0.f, 0.f, 0.f, 0.f);
        float cls = 0.f, sc = 0.f;
        if (s < nk) {
            int i = sKept[s];
            b = g_boxes[i]; cls = g_classes[i]; sc = g_scores[i];
        }
        out[s * 4 + 0] = b.x; out[s * 4 + 1] = b.y;
        out[s * 4 + 2] = b.z; out[s * 4 + 3] = b.w;
        out[MAXDET * 4 + s] = cls;
        out[MAXDET * 5 + s] = sc;
    }
}

// ---------------- K7a: fallback full mask (persistent, gated) ----------------
__global__ void k_maskF() {
    __shared__ int sdone;
    __shared__ float4 sb4[64];
    __shared__ float sa[64];
    if (threadIdx.x == 0) sdone = g_done;
    __syncthreads();
    if (sdone) return;
    int t = threadIdx.x;  // 64
    const int NT = (KW * (KW + 1)) / 2;  // 8256 triangular tiles
    for (int tile = blockIdx.x; tile < NT; tile += gridDim.x) {
        int cy = 0, rem = tile;
        while (rem >= KW - cy) { rem -= KW - cy; cy++; }
        int cx = cy + rem;
        float4 jb = g_boxes[cx * 64 + t];
        sb4[t] = jb;
        sa[t] = (jb.z - jb.x) * (jb.w - jb.y);
        float4 ib = g_boxes[cy * 64 + t];
        float ai = (ib.z - ib.x) * (ib.w - ib.y);
        __syncthreads();
        u64 bits = iou_bits(ib, ai, sb4, sa, (cx == cy) ? t + 1 : 0);
        g_mask[(size_t)(cy * 64 + t) * KW + cx] = bits;
        __syncthreads();
    }
}

// ---------------- K7b: fallback full scan (gated) + fused output ----------------
__global__ void k_scanF(float* __restrict__ out) {
    __shared__ int sdone;
    __shared__ u64 sAlive;
    __shared__ int sNk;
    if (threadIdx.x == 0) sdone = g_done;
    __syncthreads();
    if (sdone) return;
    int t = threadIdx.x;  // 128
    u64 remv = 0;
    int nk = 0;
    bool done = false;
    for (int c = 0; c < KW && !done; c++) {
        if (t == c) sAlive = (~remv) & g_validm[c];
        __syncthreads();
        while (true) {
            u64 a = sAlive;
            if (a == 0ULL) break;
            int bit = __ffsll((long long)a) - 1;
            int i = (c << 6) + bit;
            u64 row = (t >= c) ? g_mask[(size_t)i * KW + t] : 0ULL;
            remv |= row;
            if (t == 0) g_kept[nk] = i;
            nk++;
            if (t == c) sAlive = a & ~(1ULL << bit) & ~row;
            __syncthreads();
            if (nk >= MAXDET) { done = true; break; }
        }
        __syncthreads();
    }
    if (t == 0) { g_nkept = nk; sNk = nk; }
    __syncthreads();
    int n = sNk;
    for (int s = t; s < MAXDET; s += 128) {
        float4 b = make_float4(0.f, 0.f, 0.f, 0.f);
        float cls = 0.f, sc = 0.f;
        if (s < n) {
            int i = g_kept[s];
            b = g_boxes[i]; cls = g_classes[i]; sc = g_scores[i];
        }
        out[s * 4 + 0] = b.x; out[s * 4 + 1] = b.y;
        out[s * 4 + 2] = b.z; out[s * 4 + 3] = b.w;
        out[MAXDET * 4 + s] = cls;
        out[MAXDET * 5 + s] = sc;
    }
}

extern "C" void kernel_launch(void* const* d_in, const int* in_sizes, int n_in,
                              void* d_out, int out_size) {
    const float* preds = (const float*)d_in[0];
    float* out = (float*)d_out;

    static int smem_set = 0;
    if (!smem_set) {
        cudaFuncSetAttribute(k_scanS, cudaFuncAttributeMaxDynamicSharedMemorySize,
                             NSMALL * KWS * sizeof(u64));
        smem_set = 1;
    }

    k_init<<<256, 256>>>();
    k_score<<<(N_ANCH + 7) / 8, 256>>>(preds);
    k_thresh<<<1, 1024>>>();
    k_compact<<<(N_ANCH + 255) / 256, 256>>>();
    k_rank<<<dim3(CAP / RCHI, CAP / RCHJ), 256>>>();
    k_scatter<<<CAP / 256, 256>>>();
    k_gather<<<TOPK / 256, 256>>>(preds);
    k_maskS<<<dim3(16, 16), 64>>>();
    k_scanS<<<1, 512, NSMALL * KWS * sizeof(u64)>>>(out);
    k_maskF<<<2048, 64>>>();
    k_scanF<<<1, 128>>>(out);
}